// round 4
// baseline (speedup 1.0000x reference)
#include <cuda_runtime.h>
#include <cuda_fp16.h>
#include <cstdint>

// Problem constants (fixed by the dataset)
constexpr int Mrows = 8192;   // 4 * 2048
constexpr int Ncols = 4096;   // OUT_DIM
constexpr int Kdim  = 4096;   // IN_DIM
constexpr int Sseq  = 2048;
constexpr int Bbat  = 4;

// Scratch (device globals: the sanctioned no-alloc workaround)
__device__ __half g_xh[(size_t)Mrows * Kdim];   // x in fp16
__device__ __half g_wh[(size_t)Ncols * Kdim];   // W_pre in fp16
__device__ float  g_down[Mrows * 8];            // adapter down proj
__device__ float  g_o[Mrows * 8];               // adapter o (pre-up)

// ---------------------------------------------------------------------------
// Kernel 1: convert W_pre (fp32, [N,K]) -> g_wh (fp16)
// ---------------------------------------------------------------------------
__global__ void k_convw(const float* __restrict__ W) {
    size_t i = ((size_t)blockIdx.x * blockDim.x + threadIdx.x) * 8;
    float4 f0 = *reinterpret_cast<const float4*>(W + i);
    float4 f1 = *reinterpret_cast<const float4*>(W + i + 4);
    __half2 h[4];
    h[0] = __floats2half2_rn(f0.x, f0.y);
    h[1] = __floats2half2_rn(f0.z, f0.w);
    h[2] = __floats2half2_rn(f1.x, f1.y);
    h[3] = __floats2half2_rn(f1.z, f1.w);
    *reinterpret_cast<uint4*>(g_wh + i) = *reinterpret_cast<const uint4*>(h);
}

// ---------------------------------------------------------------------------
// Kernel 2: down = x @ W_down^T  ([8192,8]), fused x -> fp16 conversion.
// ---------------------------------------------------------------------------
__global__ void __launch_bounds__(256) k_down(const float* __restrict__ x,
                                              const float* __restrict__ Wd) {
    __shared__ __half wdt[8][1024];
    const int tid = threadIdx.x;
    const int wid = tid >> 5, lane = tid & 31;
    const int row = blockIdx.x * 8 + wid;
    const float* xr = x + (size_t)row * Kdim;
    __half* xhr = g_xh + (size_t)row * Kdim;

    float acc[8];
#pragma unroll
    for (int r = 0; r < 8; r++) acc[r] = 0.f;

    for (int c = 0; c < 4; c++) {
        const int kb = c * 1024;
#pragma unroll
        for (int it = 0; it < 8; it++) {
            int j4 = tid + it * 256;
            int r  = j4 >> 8;
            int kk = (j4 & 255) * 4;
            float4 w = *reinterpret_cast<const float4*>(Wd + (size_t)r * Kdim + kb + kk);
            __half2 pp[2];
            pp[0] = __floats2half2_rn(w.x, w.y);
            pp[1] = __floats2half2_rn(w.z, w.w);
            *reinterpret_cast<uint2*>(&wdt[r][kk]) = *reinterpret_cast<const uint2*>(pp);
        }
        __syncthreads();

#pragma unroll
        for (int i = 0; i < 4; i++) {
            int ko = i * 256 + lane * 8;
            float4 x0 = *reinterpret_cast<const float4*>(xr + kb + ko);
            float4 x1 = *reinterpret_cast<const float4*>(xr + kb + ko + 4);
            __half2 hx[4];
            hx[0] = __floats2half2_rn(x0.x, x0.y);
            hx[1] = __floats2half2_rn(x0.z, x0.w);
            hx[2] = __floats2half2_rn(x1.x, x1.y);
            hx[3] = __floats2half2_rn(x1.z, x1.w);
            *reinterpret_cast<uint4*>(xhr + kb + ko) = *reinterpret_cast<const uint4*>(hx);
#pragma unroll
            for (int r = 0; r < 8; r++) {
                uint4 wv = *reinterpret_cast<const uint4*>(&wdt[r][ko]);
                const __half2* wh = reinterpret_cast<const __half2*>(&wv);
                float2 w0 = __half22float2(wh[0]);
                float2 w1 = __half22float2(wh[1]);
                float2 w2 = __half22float2(wh[2]);
                float2 w3 = __half22float2(wh[3]);
                acc[r] += x0.x * w0.x + x0.y * w0.y + x0.z * w1.x + x0.w * w1.y
                        + x1.x * w2.x + x1.y * w2.y + x1.z * w3.x + x1.w * w3.y;
            }
        }
        __syncthreads();
    }
#pragma unroll
    for (int off = 16; off; off >>= 1)
#pragma unroll
        for (int r = 0; r < 8; r++) acc[r] += __shfl_xor_sync(0xffffffffu, acc[r], off);
    if (lane == 0) {
        *reinterpret_cast<float4*>(g_down + (size_t)row * 8)     = make_float4(acc[0], acc[1], acc[2], acc[3]);
        *reinterpret_cast<float4*>(g_down + (size_t)row * 8 + 4) = make_float4(acc[4], acc[5], acc[6], acc[7]);
    }
}

// ---------------------------------------------------------------------------
// Kernel 3: adapter attention -> g_o = (softmax(qk)v) @ W_o^T  [8192,8]
// ---------------------------------------------------------------------------
__global__ void __launch_bounds__(128) k_attn(const float* __restrict__ Wqkv,
                                              const float* __restrict__ Wo) {
    __shared__ __half2 kv[Sseq * 4];
    __shared__ float wq[96];
    __shared__ float wo[32];
    const int tid = threadIdx.x;
    const int b = blockIdx.y, qt = blockIdx.x;

    if (tid < 96) wq[tid] = Wqkv[tid];
    if (tid < 32) wo[tid] = Wo[tid];
    __syncthreads();

    for (int j = tid; j < Sseq; j += 128) {
        const float* dp = g_down + (size_t)(b * Sseq + j) * 8;
        float4 d0 = *reinterpret_cast<const float4*>(dp);
        float4 d1 = *reinterpret_cast<const float4*>(dp + 4);
        float kd[4], vd[4];
#pragma unroll
        for (int d = 0; d < 4; d++) {
            const float* w = wq + (4 + d) * 8;
            kd[d] = d0.x*w[0] + d0.y*w[1] + d0.z*w[2] + d0.w*w[3]
                  + d1.x*w[4] + d1.y*w[5] + d1.z*w[6] + d1.w*w[7];
            const float* w2 = wq + (8 + d) * 8;
            vd[d] = d0.x*w2[0] + d0.y*w2[1] + d0.z*w2[2] + d0.w*w2[3]
                  + d1.x*w2[4] + d1.y*w2[5] + d1.z*w2[6] + d1.w*w2[7];
        }
        kv[j * 4 + 0] = __floats2half2_rn(kd[0], kd[1]);
        kv[j * 4 + 1] = __floats2half2_rn(kd[2], kd[3]);
        kv[j * 4 + 2] = __floats2half2_rn(vd[0], vd[1]);
        kv[j * 4 + 3] = __floats2half2_rn(vd[2], vd[3]);
    }

    const int qrow = b * Sseq + qt * 128 + tid;
    const float* dq = g_down + (size_t)qrow * 8;
    float4 d0 = *reinterpret_cast<const float4*>(dq);
    float4 d1 = *reinterpret_cast<const float4*>(dq + 4);
    float q[4];
#pragma unroll
    for (int d = 0; d < 4; d++) {
        const float* w = wq + d * 8;
        q[d] = d0.x*w[0] + d0.y*w[1] + d0.z*w[2] + d0.w*w[3]
             + d1.x*w[4] + d1.y*w[5] + d1.z*w[6] + d1.w*w[7];
    }
    __syncthreads();

    float l = 0.f, a0 = 0.f, a1 = 0.f, a2 = 0.f, a3 = 0.f;
    const uint4* kv4 = reinterpret_cast<const uint4*>(kv);
    for (int j = 0; j < Sseq; j++) {
        uint4 pk = kv4[j];
        const __half2* ph = reinterpret_cast<const __half2*>(&pk);
        float2 k01 = __half22float2(ph[0]);
        float2 k23 = __half22float2(ph[1]);
        float2 v01 = __half22float2(ph[2]);
        float2 v23 = __half22float2(ph[3]);
        float s = (q[0]*k01.x + q[1]*k01.y + q[2]*k23.x + q[3]*k23.y) * 0.5f;
        float p = __expf(s);
        l += p;
        a0 += p * v01.x; a1 += p * v01.y; a2 += p * v23.x; a3 += p * v23.y;
    }
    float rl = 1.f / l;
    float c0 = a0 * rl, c1 = a1 * rl, c2 = a2 * rl, c3 = a3 * rl;
    float ov[8];
#pragma unroll
    for (int r = 0; r < 8; r++)
        ov[r] = c0*wo[r*4] + c1*wo[r*4+1] + c2*wo[r*4+2] + c3*wo[r*4+3];
    *reinterpret_cast<float4*>(g_o + (size_t)qrow * 8)     = make_float4(ov[0], ov[1], ov[2], ov[3]);
    *reinterpret_cast<float4*>(g_o + (size_t)qrow * 8 + 4) = make_float4(ov[4], ov[5], ov[6], ov[7]);
}

// ---------------------------------------------------------------------------
// Kernel 4: main GEMM out = xh @ wh^T (+ epilogue: b_pre + (o@W_up^T)*diag_b*4)
// 128x128x32 tiles, fp16 mma.sync m16n8k16, 4-stage cp.async, 2 CTAs/SM.
// ---------------------------------------------------------------------------
#define LDMX4(R0, R1, R2, R3, addr)                                            \
    asm volatile("ldmatrix.sync.aligned.m8n8.x4.shared.b16 {%0,%1,%2,%3}, [%4];" \
                 : "=r"(R0), "=r"(R1), "=r"(R2), "=r"(R3) : "r"(addr))

#define MMA16816(D0, D1, D2, D3, A0, A1, A2, A3, B0, B1)                       \
    asm volatile("mma.sync.aligned.m16n8k16.row.col.f32.f16.f16.f32 "          \
                 "{%0,%1,%2,%3}, {%4,%5,%6,%7}, {%8,%9}, {%0,%1,%2,%3};"       \
                 : "+f"(D0), "+f"(D1), "+f"(D2), "+f"(D3)                      \
                 : "r"(A0), "r"(A1), "r"(A2), "r"(A3), "r"(B0), "r"(B1))

#define CPASYNC16(dst, src)                                                    \
    asm volatile("cp.async.cg.shared.global [%0], [%1], 16;" ::"r"(dst), "l"(src))
#define CPCOMMIT()  asm volatile("cp.async.commit_group;")
#define CPWAIT(N)   asm volatile("cp.async.wait_group %0;" :: "n"(N))

constexpr int LDT = 40;          // smem row stride (halves): 32 + 8 pad
constexpr int STG_H = 128 * LDT; // halves per stage tile (A or B)
constexpr int STAGES = 4;
constexpr size_t SMEM_BYTES = (size_t)2 * STAGES * STG_H * sizeof(__half); // 81920

__device__ __forceinline__ uint32_t smem_u32(const void* p) {
    uint32_t a;
    asm("{ .reg .u64 t; cvta.to.shared.u64 t, %1; cvt.u32.u64 %0, t; }" : "=r"(a) : "l"(p));
    return a;
}

__global__ void __launch_bounds__(256, 2) k_gemm(const float* __restrict__ Wup,
                                                 const float* __restrict__ dbv,
                                                 const float* __restrict__ bpv,
                                                 float* __restrict__ out) {
    extern __shared__ __half sm[];
    const int tid = threadIdx.x;
    const int wid = tid >> 5, lane = tid & 31;
    const int wm = wid >> 2, wn = wid & 3;       // warp grid 2 x 4, warp tile 64x32
    const int m0 = blockIdx.y * 128, n0 = blockIdx.x * 128;

    const uint32_t smb = smem_u32(sm);

    // global->smem load mapping: per stage each thread: 2 A + 2 B 16B chunks
    const int rA = tid >> 2;            // 0..63
    const int cA = (tid & 3) * 8;       // 0,8,16,24 halves
    const __half* pA0 = g_xh + (size_t)(m0 + rA) * Kdim + cA;
    const __half* pA1 = pA0 + (size_t)64 * Kdim;
    const __half* pB0 = g_wh + (size_t)(n0 + rA) * Kdim + cA;
    const __half* pB1 = pB0 + (size_t)64 * Kdim;
    const uint32_t dof0 = (uint32_t)((rA * LDT + cA) * 2);
    const uint32_t dof1 = (uint32_t)(((rA + 64) * LDT + cA) * 2);

#define LOAD_STAGE(J, S) do {                                                  \
    const uint32_t _a = smb + (uint32_t)(S) * (STG_H * 2);                     \
    const uint32_t _b = smb + (uint32_t)(STAGES + (S)) * (STG_H * 2);          \
    const size_t _ko = (size_t)(J) * 32;                                       \
    CPASYNC16(_a + dof0, pA0 + _ko); CPASYNC16(_a + dof1, pA1 + _ko);          \
    CPASYNC16(_b + dof0, pB0 + _ko); CPASYNC16(_b + dof1, pB1 + _ko);          \
} while (0)

    // ldmatrix per-lane offsets
    const int arow = lane & 15, acol = ((lane >> 4) << 3);
    const int brow = (lane & 7) + ((lane >> 4) << 3), bcol = (((lane >> 3) & 1) << 3);

    float acc[4][4][4];
#pragma unroll
    for (int i = 0; i < 4; i++)
#pragma unroll
        for (int j = 0; j < 4; j++)
#pragma unroll
            for (int e = 0; e < 4; e++) acc[i][j][e] = 0.f;

    // prologue: stages 0..2
#pragma unroll
    for (int s = 0; s < STAGES - 1; s++) { LOAD_STAGE(s, s); CPCOMMIT(); }

    const int NIT = Kdim / 32;  // 128
    for (int it = 0; it < NIT; ++it) {
        const int cur = it & (STAGES - 1);
        CPWAIT(STAGES - 2);          // stage `it` complete; 2 groups may fly
        __syncthreads();             // all warps done with slot being refilled
        if (it + STAGES - 1 < NIT) LOAD_STAGE(it + STAGES - 1, (it + STAGES - 1) & (STAGES - 1));
        CPCOMMIT();

        const uint32_t abase = smb + (uint32_t)cur * (STG_H * 2);
        const uint32_t bbase = smb + (uint32_t)(STAGES + cur) * (STG_H * 2);
#pragma unroll
        for (int ks = 0; ks < 2; ks++) {
            uint32_t a[4][4], bf[2][4];
#pragma unroll
            for (int mt = 0; mt < 4; mt++) {
                uint32_t ad = abase + (uint32_t)(((wm * 64 + mt * 16 + arow) * LDT + ks * 16 + acol) * 2);
                LDMX4(a[mt][0], a[mt][1], a[mt][2], a[mt][3], ad);
            }
#pragma unroll
            for (int pt = 0; pt < 2; pt++) {
                uint32_t bd = bbase + (uint32_t)(((wn * 32 + pt * 16 + brow) * LDT + ks * 16 + bcol) * 2);
                LDMX4(bf[pt][0], bf[pt][1], bf[pt][2], bf[pt][3], bd);
            }
#pragma unroll
            for (int mt = 0; mt < 4; mt++)
#pragma unroll
                for (int nt = 0; nt < 4; nt++) {
                    const int pt = nt >> 1, h = (nt & 1) * 2;
                    MMA16816(acc[mt][nt][0], acc[mt][nt][1], acc[mt][nt][2], acc[mt][nt][3],
                             a[mt][0], a[mt][1], a[mt][2], a[mt][3],
                             bf[pt][h], bf[pt][h + 1]);
                }
        }
    }
    CPWAIT(0);
    __syncthreads();

    // Epilogue staging in smem (reuse mainloop buffers)
    float* oS   = reinterpret_cast<float*>(sm);            // [128][8]
    float* wupS = oS + 1024;                               // [128][8]
    float* dbS  = wupS + 1024;                             // [128]
    float* bpS  = dbS + 128;                               // [128]
    {
        float4* d0 = reinterpret_cast<float4*>(oS);
        float4* d1 = reinterpret_cast<float4*>(wupS);
        d0[tid] = reinterpret_cast<const float4*>(g_o + (size_t)m0 * 8)[tid];
        d1[tid] = reinterpret_cast<const float4*>(Wup + (size_t)n0 * 8)[tid];
        if (tid < 128) { dbS[tid] = dbv[n0 + tid] * 4.0f; bpS[tid] = bpv[n0 + tid]; }
    }
    __syncthreads();

    const int g = lane >> 2, tg = lane & 3;
#pragma unroll
    for (int mt = 0; mt < 4; mt++) {
#pragma unroll
        for (int e2 = 0; e2 < 2; e2++) {
            const int r = wm * 64 + mt * 16 + g + e2 * 8;
            float4 o0 = *reinterpret_cast<const float4*>(oS + r * 8);
            float4 o1 = *reinterpret_cast<const float4*>(oS + r * 8 + 4);
#pragma unroll
            for (int nt = 0; nt < 4; nt++) {
                const int c = wn * 32 + nt * 8 + tg * 2;
                float2 res;
#pragma unroll
                for (int cc = 0; cc < 2; cc++) {
                    float4 u0 = *reinterpret_cast<const float4*>(wupS + (c + cc) * 8);
                    float4 u1 = *reinterpret_cast<const float4*>(wupS + (c + cc) * 8 + 4);
                    float ad = o0.x*u0.x + o0.y*u0.y + o0.z*u0.z + o0.w*u0.w
                             + o1.x*u1.x + o1.y*u1.y + o1.z*u1.z + o1.w*u1.w;
                    float v = acc[mt][nt][e2 * 2 + cc] + bpS[c + cc] + ad * dbS[c + cc];
                    if (cc) res.y = v; else res.x = v;
                }
                *reinterpret_cast<float2*>(out + (size_t)(m0 + r) * Ncols + n0 + c) = res;
            }
        }
    }
}

// ---------------------------------------------------------------------------
extern "C" void kernel_launch(void* const* d_in, const int* in_sizes, int n_in,
                              void* d_out, int out_size) {
    const float* x     = (const float*)d_in[0];
    const float* Wpre  = (const float*)d_in[1];
    const float* bpre  = (const float*)d_in[2];
    const float* Wd    = (const float*)d_in[3];
    const float* Wqkv  = (const float*)d_in[4];
    const float* Wo    = (const float*)d_in[5];
    const float* Wup   = (const float*)d_in[6];
    const float* diagb = (const float*)d_in[7];
    float* out = (float*)d_out;

    cudaFuncSetAttribute(k_gemm, cudaFuncAttributeMaxDynamicSharedMemorySize,
                         (int)SMEM_BYTES);

    k_convw<<<(unsigned)(((size_t)Ncols * Kdim) / 2048), 256>>>(Wpre);
    k_down<<<Mrows / 8, 256>>>(x, Wd);
    k_attn<<<dim3(Sseq / 128, Bbat), 128>>>(Wqkv, Wo);
    k_gemm<<<dim3(Ncols / 128, Mrows / 128), 256, SMEM_BYTES>>>(Wup, diagb, bpre, out);
}

// round 5
// speedup vs baseline: 1.0006x; 1.0006x over previous
#include <cuda_runtime.h>
#include <cuda_fp16.h>
#include <cstdint>

// Problem constants (fixed by the dataset)
constexpr int Mrows = 8192;   // 4 * 2048
constexpr int Ncols = 4096;   // OUT_DIM
constexpr int Kdim  = 4096;   // IN_DIM
constexpr int Sseq  = 2048;
constexpr int Bbat  = 4;

// Scratch (device globals: the sanctioned no-alloc workaround)
__device__ __half g_xh[(size_t)Mrows * Kdim];   // x in fp16
__device__ __half g_wh[(size_t)Ncols * Kdim];   // W_pre in fp16
__device__ float  g_down[Mrows * 8];            // adapter down proj
__device__ float  g_o[Mrows * 8];               // adapter o (pre-up)

// ---------------------------------------------------------------------------
// Kernel 1: convert W_pre (fp32, [N,K]) -> g_wh (fp16)
// ---------------------------------------------------------------------------
__global__ void k_convw(const float* __restrict__ W) {
    size_t i = ((size_t)blockIdx.x * blockDim.x + threadIdx.x) * 8;
    float4 f0 = *reinterpret_cast<const float4*>(W + i);
    float4 f1 = *reinterpret_cast<const float4*>(W + i + 4);
    __half2 h[4];
    h[0] = __floats2half2_rn(f0.x, f0.y);
    h[1] = __floats2half2_rn(f0.z, f0.w);
    h[2] = __floats2half2_rn(f1.x, f1.y);
    h[3] = __floats2half2_rn(f1.z, f1.w);
    *reinterpret_cast<uint4*>(g_wh + i) = *reinterpret_cast<const uint4*>(h);
}

// ---------------------------------------------------------------------------
// Kernel 2: down = x @ W_down^T  ([8192,8]), fused x -> fp16 conversion.
// ---------------------------------------------------------------------------
__global__ void __launch_bounds__(256) k_down(const float* __restrict__ x,
                                              const float* __restrict__ Wd) {
    __shared__ __half wdt[8][1024];
    const int tid = threadIdx.x;
    const int wid = tid >> 5, lane = tid & 31;
    const int row = blockIdx.x * 8 + wid;
    const float* xr = x + (size_t)row * Kdim;
    __half* xhr = g_xh + (size_t)row * Kdim;

    float acc[8];
#pragma unroll
    for (int r = 0; r < 8; r++) acc[r] = 0.f;

    for (int c = 0; c < 4; c++) {
        const int kb = c * 1024;
#pragma unroll
        for (int it = 0; it < 8; it++) {
            int j4 = tid + it * 256;
            int r  = j4 >> 8;
            int kk = (j4 & 255) * 4;
            float4 w = *reinterpret_cast<const float4*>(Wd + (size_t)r * Kdim + kb + kk);
            __half2 pp[2];
            pp[0] = __floats2half2_rn(w.x, w.y);
            pp[1] = __floats2half2_rn(w.z, w.w);
            *reinterpret_cast<uint2*>(&wdt[r][kk]) = *reinterpret_cast<const uint2*>(pp);
        }
        __syncthreads();

#pragma unroll
        for (int i = 0; i < 4; i++) {
            int ko = i * 256 + lane * 8;
            float4 x0 = *reinterpret_cast<const float4*>(xr + kb + ko);
            float4 x1 = *reinterpret_cast<const float4*>(xr + kb + ko + 4);
            __half2 hx[4];
            hx[0] = __floats2half2_rn(x0.x, x0.y);
            hx[1] = __floats2half2_rn(x0.z, x0.w);
            hx[2] = __floats2half2_rn(x1.x, x1.y);
            hx[3] = __floats2half2_rn(x1.z, x1.w);
            *reinterpret_cast<uint4*>(xhr + kb + ko) = *reinterpret_cast<const uint4*>(hx);
#pragma unroll
            for (int r = 0; r < 8; r++) {
                uint4 wv = *reinterpret_cast<const uint4*>(&wdt[r][ko]);
                const __half2* wh = reinterpret_cast<const __half2*>(&wv);
                float2 w0 = __half22float2(wh[0]);
                float2 w1 = __half22float2(wh[1]);
                float2 w2 = __half22float2(wh[2]);
                float2 w3 = __half22float2(wh[3]);
                acc[r] += x0.x * w0.x + x0.y * w0.y + x0.z * w1.x + x0.w * w1.y
                        + x1.x * w2.x + x1.y * w2.y + x1.z * w3.x + x1.w * w3.y;
            }
        }
        __syncthreads();
    }
#pragma unroll
    for (int off = 16; off; off >>= 1)
#pragma unroll
        for (int r = 0; r < 8; r++) acc[r] += __shfl_xor_sync(0xffffffffu, acc[r], off);
    if (lane == 0) {
        *reinterpret_cast<float4*>(g_down + (size_t)row * 8)     = make_float4(acc[0], acc[1], acc[2], acc[3]);
        *reinterpret_cast<float4*>(g_down + (size_t)row * 8 + 4) = make_float4(acc[4], acc[5], acc[6], acc[7]);
    }
}

// ---------------------------------------------------------------------------
// Kernel 3: adapter attention -> g_o = (softmax(qk)v) @ W_o^T  [8192,8]
// ---------------------------------------------------------------------------
__global__ void __launch_bounds__(128) k_attn(const float* __restrict__ Wqkv,
                                              const float* __restrict__ Wo) {
    __shared__ __half2 kv[Sseq * 4];
    __shared__ float wq[96];
    __shared__ float wo[32];
    const int tid = threadIdx.x;
    const int b = blockIdx.y, qt = blockIdx.x;

    if (tid < 96) wq[tid] = Wqkv[tid];
    if (tid < 32) wo[tid] = Wo[tid];
    __syncthreads();

    for (int j = tid; j < Sseq; j += 128) {
        const float* dp = g_down + (size_t)(b * Sseq + j) * 8;
        float4 d0 = *reinterpret_cast<const float4*>(dp);
        float4 d1 = *reinterpret_cast<const float4*>(dp + 4);
        float kd[4], vd[4];
#pragma unroll
        for (int d = 0; d < 4; d++) {
            const float* w = wq + (4 + d) * 8;
            kd[d] = d0.x*w[0] + d0.y*w[1] + d0.z*w[2] + d0.w*w[3]
                  + d1.x*w[4] + d1.y*w[5] + d1.z*w[6] + d1.w*w[7];
            const float* w2 = wq + (8 + d) * 8;
            vd[d] = d0.x*w2[0] + d0.y*w2[1] + d0.z*w2[2] + d0.w*w2[3]
                  + d1.x*w2[4] + d1.y*w2[5] + d1.z*w2[6] + d1.w*w2[7];
        }
        kv[j * 4 + 0] = __floats2half2_rn(kd[0], kd[1]);
        kv[j * 4 + 1] = __floats2half2_rn(kd[2], kd[3]);
        kv[j * 4 + 2] = __floats2half2_rn(vd[0], vd[1]);
        kv[j * 4 + 3] = __floats2half2_rn(vd[2], vd[3]);
    }

    const int qrow = b * Sseq + qt * 128 + tid;
    const float* dq = g_down + (size_t)qrow * 8;
    float4 d0 = *reinterpret_cast<const float4*>(dq);
    float4 d1 = *reinterpret_cast<const float4*>(dq + 4);
    float q[4];
#pragma unroll
    for (int d = 0; d < 4; d++) {
        const float* w = wq + d * 8;
        q[d] = d0.x*w[0] + d0.y*w[1] + d0.z*w[2] + d0.w*w[3]
             + d1.x*w[4] + d1.y*w[5] + d1.z*w[6] + d1.w*w[7];
    }
    __syncthreads();

    float l = 0.f, a0 = 0.f, a1 = 0.f, a2 = 0.f, a3 = 0.f;
    const uint4* kv4 = reinterpret_cast<const uint4*>(kv);
    for (int j = 0; j < Sseq; j++) {
        uint4 pk = kv4[j];
        const __half2* ph = reinterpret_cast<const __half2*>(&pk);
        float2 k01 = __half22float2(ph[0]);
        float2 k23 = __half22float2(ph[1]);
        float2 v01 = __half22float2(ph[2]);
        float2 v23 = __half22float2(ph[3]);
        float s = (q[0]*k01.x + q[1]*k01.y + q[2]*k23.x + q[3]*k23.y) * 0.5f;
        float p = __expf(s);
        l += p;
        a0 += p * v01.x; a1 += p * v01.y; a2 += p * v23.x; a3 += p * v23.y;
    }
    float rl = 1.f / l;
    float c0 = a0 * rl, c1 = a1 * rl, c2 = a2 * rl, c3 = a3 * rl;
    float ov[8];
#pragma unroll
    for (int r = 0; r < 8; r++)
        ov[r] = c0*wo[r*4] + c1*wo[r*4+1] + c2*wo[r*4+2] + c3*wo[r*4+3];
    *reinterpret_cast<float4*>(g_o + (size_t)qrow * 8)     = make_float4(ov[0], ov[1], ov[2], ov[3]);
    *reinterpret_cast<float4*>(g_o + (size_t)qrow * 8 + 4) = make_float4(ov[4], ov[5], ov[6], ov[7]);
}

// ---------------------------------------------------------------------------
// Kernel 4: main GEMM out = xh @ wh^T (+ epilogue: b_pre + (o@W_up^T)*diag_b*4)
// 128x128x32 tiles, fp16 mma.sync m16n8k16, 4-stage cp.async, 2 CTAs/SM.
// ---------------------------------------------------------------------------
#define LDMX4(R0, R1, R2, R3, addr)                                            \
    asm volatile("ldmatrix.sync.aligned.m8n8.x4.shared.b16 {%0,%1,%2,%3}, [%4];" \
                 : "=r"(R0), "=r"(R1), "=r"(R2), "=r"(R3) : "r"(addr))

#define MMA16816(D0, D1, D2, D3, A0, A1, A2, A3, B0, B1)                       \
    asm volatile("mma.sync.aligned.m16n8k16.row.col.f32.f16.f16.f32 "          \
                 "{%0,%1,%2,%3}, {%4,%5,%6,%7}, {%8,%9}, {%0,%1,%2,%3};"       \
                 : "+f"(D0), "+f"(D1), "+f"(D2), "+f"(D3)                      \
                 : "r"(A0), "r"(A1), "r"(A2), "r"(A3), "r"(B0), "r"(B1))

#define CPASYNC16(dst, src)                                                    \
    asm volatile("cp.async.cg.shared.global [%0], [%1], 16;" ::"r"(dst), "l"(src))
#define CPCOMMIT()  asm volatile("cp.async.commit_group;")
#define CPWAIT(N)   asm volatile("cp.async.wait_group %0;" :: "n"(N))

constexpr int LDT = 40;          // smem row stride (halves): 32 + 8 pad
constexpr int STG_H = 128 * LDT; // halves per stage tile (A or B)
constexpr int STAGES = 4;
constexpr size_t SMEM_BYTES = (size_t)2 * STAGES * STG_H * sizeof(__half); // 81920

__device__ __forceinline__ uint32_t smem_u32(const void* p) {
    uint32_t a;
    asm("{ .reg .u64 t; cvta.to.shared.u64 t, %1; cvt.u32.u64 %0, t; }" : "=r"(a) : "l"(p));
    return a;
}

__global__ void __launch_bounds__(256, 2) k_gemm(const float* __restrict__ Wup,
                                                 const float* __restrict__ dbv,
                                                 const float* __restrict__ bpv,
                                                 float* __restrict__ out) {
    extern __shared__ __half sm[];
    const int tid = threadIdx.x;
    const int wid = tid >> 5, lane = tid & 31;
    const int wm = wid >> 2, wn = wid & 3;       // warp grid 2 x 4, warp tile 64x32
    const int m0 = blockIdx.y * 128, n0 = blockIdx.x * 128;

    const uint32_t smb = smem_u32(sm);

    // global->smem load mapping: per stage each thread: 2 A + 2 B 16B chunks
    const int rA = tid >> 2;            // 0..63
    const int cA = (tid & 3) * 8;       // 0,8,16,24 halves
    const __half* pA0 = g_xh + (size_t)(m0 + rA) * Kdim + cA;
    const __half* pA1 = pA0 + (size_t)64 * Kdim;
    const __half* pB0 = g_wh + (size_t)(n0 + rA) * Kdim + cA;
    const __half* pB1 = pB0 + (size_t)64 * Kdim;
    const uint32_t dof0 = (uint32_t)((rA * LDT + cA) * 2);
    const uint32_t dof1 = (uint32_t)(((rA + 64) * LDT + cA) * 2);

#define LOAD_STAGE(J, S) do {                                                  \
    const uint32_t _a = smb + (uint32_t)(S) * (STG_H * 2);                     \
    const uint32_t _b = smb + (uint32_t)(STAGES + (S)) * (STG_H * 2);          \
    const size_t _ko = (size_t)(J) * 32;                                       \
    CPASYNC16(_a + dof0, pA0 + _ko); CPASYNC16(_a + dof1, pA1 + _ko);          \
    CPASYNC16(_b + dof0, pB0 + _ko); CPASYNC16(_b + dof1, pB1 + _ko);          \
} while (0)

    // ldmatrix per-lane offsets
    const int arow = lane & 15, acol = ((lane >> 4) << 3);
    const int brow = (lane & 7) + ((lane >> 4) << 3), bcol = (((lane >> 3) & 1) << 3);

    float acc[4][4][4];
#pragma unroll
    for (int i = 0; i < 4; i++)
#pragma unroll
        for (int j = 0; j < 4; j++)
#pragma unroll
            for (int e = 0; e < 4; e++) acc[i][j][e] = 0.f;

    // prologue: stages 0..2
#pragma unroll
    for (int s = 0; s < STAGES - 1; s++) { LOAD_STAGE(s, s); CPCOMMIT(); }

    const int NIT = Kdim / 32;  // 128
    for (int it = 0; it < NIT; ++it) {
        const int cur = it & (STAGES - 1);
        CPWAIT(STAGES - 2);          // stage `it` complete; 2 groups may fly
        __syncthreads();             // all warps done with slot being refilled
        if (it + STAGES - 1 < NIT) LOAD_STAGE(it + STAGES - 1, (it + STAGES - 1) & (STAGES - 1));
        CPCOMMIT();

        const uint32_t abase = smb + (uint32_t)cur * (STG_H * 2);
        const uint32_t bbase = smb + (uint32_t)(STAGES + cur) * (STG_H * 2);
#pragma unroll
        for (int ks = 0; ks < 2; ks++) {
            uint32_t a[4][4], bf[2][4];
#pragma unroll
            for (int mt = 0; mt < 4; mt++) {
                uint32_t ad = abase + (uint32_t)(((wm * 64 + mt * 16 + arow) * LDT + ks * 16 + acol) * 2);
                LDMX4(a[mt][0], a[mt][1], a[mt][2], a[mt][3], ad);
            }
#pragma unroll
            for (int pt = 0; pt < 2; pt++) {
                uint32_t bd = bbase + (uint32_t)(((wn * 32 + pt * 16 + brow) * LDT + ks * 16 + bcol) * 2);
                LDMX4(bf[pt][0], bf[pt][1], bf[pt][2], bf[pt][3], bd);
            }
#pragma unroll
            for (int mt = 0; mt < 4; mt++)
#pragma unroll
                for (int nt = 0; nt < 4; nt++) {
                    const int pt = nt >> 1, h = (nt & 1) * 2;
                    MMA16816(acc[mt][nt][0], acc[mt][nt][1], acc[mt][nt][2], acc[mt][nt][3],
                             a[mt][0], a[mt][1], a[mt][2], a[mt][3],
                             bf[pt][h], bf[pt][h + 1]);
                }
        }
    }
    CPWAIT(0);
    __syncthreads();

    // Epilogue staging in smem (reuse mainloop buffers)
    float* oS   = reinterpret_cast<float*>(sm);            // [128][8]
    float* wupS = oS + 1024;                               // [128][8]
    float* dbS  = wupS + 1024;                             // [128]
    float* bpS  = dbS + 128;                               // [128]
    {
        float4* d0 = reinterpret_cast<float4*>(oS);
        float4* d1 = reinterpret_cast<float4*>(wupS);
        d0[tid] = reinterpret_cast<const float4*>(g_o + (size_t)m0 * 8)[tid];
        d1[tid] = reinterpret_cast<const float4*>(Wup + (size_t)n0 * 8)[tid];
        if (tid < 128) { dbS[tid] = dbv[n0 + tid] * 4.0f; bpS[tid] = bpv[n0 + tid]; }
    }
    __syncthreads();

    const int g = lane >> 2, tg = lane & 3;
#pragma unroll
    for (int mt = 0; mt < 4; mt++) {
#pragma unroll
        for (int e2 = 0; e2 < 2; e2++) {
            const int r = wm * 64 + mt * 16 + g + e2 * 8;
            float4 o0 = *reinterpret_cast<const float4*>(oS + r * 8);
            float4 o1 = *reinterpret_cast<const float4*>(oS + r * 8 + 4);
#pragma unroll
            for (int nt = 0; nt < 4; nt++) {
                const int c = wn * 32 + nt * 8 + tg * 2;
                float2 res;
#pragma unroll
                for (int cc = 0; cc < 2; cc++) {
                    float4 u0 = *reinterpret_cast<const float4*>(wupS + (c + cc) * 8);
                    float4 u1 = *reinterpret_cast<const float4*>(wupS + (c + cc) * 8 + 4);
                    float ad = o0.x*u0.x + o0.y*u0.y + o0.z*u0.z + o0.w*u0.w
                             + o1.x*u1.x + o1.y*u1.y + o1.z*u1.z + o1.w*u1.w;
                    float v = acc[mt][nt][e2 * 2 + cc] + bpS[c + cc] + ad * dbS[c + cc];
                    if (cc) res.y = v; else res.x = v;
                }
                *reinterpret_cast<float2*>(out + (size_t)(m0 + r) * Ncols + n0 + c) = res;
            }
        }
    }
}

// ---------------------------------------------------------------------------
extern "C" void kernel_launch(void* const* d_in, const int* in_sizes, int n_in,
                              void* d_out, int out_size) {
    const float* x     = (const float*)d_in[0];
    const float* Wpre  = (const float*)d_in[1];
    const float* bpre  = (const float*)d_in[2];
    const float* Wd    = (const float*)d_in[3];
    const float* Wqkv  = (const float*)d_in[4];
    const float* Wo    = (const float*)d_in[5];
    const float* Wup   = (const float*)d_in[6];
    const float* diagb = (const float*)d_in[7];
    float* out = (float*)d_out;

    cudaFuncSetAttribute(k_gemm, cudaFuncAttributeMaxDynamicSharedMemorySize,
                         (int)SMEM_BYTES);

    k_convw<<<(unsigned)(((size_t)Ncols * Kdim) / 2048), 256>>>(Wpre);
    k_down<<<Mrows / 8, 256>>>(x, Wd);
    k_attn<<<dim3(Sseq / 128, Bbat), 128>>>(Wqkv, Wo);
    k_gemm<<<dim3(Ncols / 128, Mrows / 128), 256, SMEM_BYTES>>>(Wup, diagb, bpre, out);
}

// round 6
// speedup vs baseline: 1.0010x; 1.0004x over previous
#include <cuda_runtime.h>
#include <cuda_fp16.h>
#include <cstdint>

// Problem constants (fixed by the dataset)
constexpr int Mrows = 8192;   // 4 * 2048
constexpr int Ncols = 4096;   // OUT_DIM
constexpr int Kdim  = 4096;   // IN_DIM
constexpr int Sseq  = 2048;
constexpr int Bbat  = 4;

// Scratch (device globals: the sanctioned no-alloc workaround)
__device__ __half g_xh[(size_t)Mrows * Kdim];   // x in fp16
__device__ __half g_wh[(size_t)Ncols * Kdim];   // W_pre in fp16
__device__ float  g_down[Mrows * 8];            // adapter down proj
__device__ float  g_o[Mrows * 8];               // adapter o (pre-up)

// ---------------------------------------------------------------------------
// Kernel 1: convert W_pre (fp32, [N,K]) -> g_wh (fp16)
// ---------------------------------------------------------------------------
__global__ void k_convw(const float* __restrict__ W) {
    size_t i = ((size_t)blockIdx.x * blockDim.x + threadIdx.x) * 8;
    float4 f0 = *reinterpret_cast<const float4*>(W + i);
    float4 f1 = *reinterpret_cast<const float4*>(W + i + 4);
    __half2 h[4];
    h[0] = __floats2half2_rn(f0.x, f0.y);
    h[1] = __floats2half2_rn(f0.z, f0.w);
    h[2] = __floats2half2_rn(f1.x, f1.y);
    h[3] = __floats2half2_rn(f1.z, f1.w);
    *reinterpret_cast<uint4*>(g_wh + i) = *reinterpret_cast<const uint4*>(h);
}

// ---------------------------------------------------------------------------
// Kernel 2: down = x @ W_down^T  ([8192,8]), fused x -> fp16 conversion.
// ---------------------------------------------------------------------------
__global__ void __launch_bounds__(256) k_down(const float* __restrict__ x,
                                              const float* __restrict__ Wd) {
    __shared__ __half wdt[8][1024];
    const int tid = threadIdx.x;
    const int wid = tid >> 5, lane = tid & 31;
    const int row = blockIdx.x * 8 + wid;
    const float* xr = x + (size_t)row * Kdim;
    __half* xhr = g_xh + (size_t)row * Kdim;

    float acc[8];
#pragma unroll
    for (int r = 0; r < 8; r++) acc[r] = 0.f;

    for (int c = 0; c < 4; c++) {
        const int kb = c * 1024;
#pragma unroll
        for (int it = 0; it < 8; it++) {
            int j4 = tid + it * 256;
            int r  = j4 >> 8;
            int kk = (j4 & 255) * 4;
            float4 w = *reinterpret_cast<const float4*>(Wd + (size_t)r * Kdim + kb + kk);
            __half2 pp[2];
            pp[0] = __floats2half2_rn(w.x, w.y);
            pp[1] = __floats2half2_rn(w.z, w.w);
            *reinterpret_cast<uint2*>(&wdt[r][kk]) = *reinterpret_cast<const uint2*>(pp);
        }
        __syncthreads();

#pragma unroll
        for (int i = 0; i < 4; i++) {
            int ko = i * 256 + lane * 8;
            float4 x0 = *reinterpret_cast<const float4*>(xr + kb + ko);
            float4 x1 = *reinterpret_cast<const float4*>(xr + kb + ko + 4);
            __half2 hx[4];
            hx[0] = __floats2half2_rn(x0.x, x0.y);
            hx[1] = __floats2half2_rn(x0.z, x0.w);
            hx[2] = __floats2half2_rn(x1.x, x1.y);
            hx[3] = __floats2half2_rn(x1.z, x1.w);
            *reinterpret_cast<uint4*>(xhr + kb + ko) = *reinterpret_cast<const uint4*>(hx);
#pragma unroll
            for (int r = 0; r < 8; r++) {
                uint4 wv = *reinterpret_cast<const uint4*>(&wdt[r][ko]);
                const __half2* wh = reinterpret_cast<const __half2*>(&wv);
                float2 w0 = __half22float2(wh[0]);
                float2 w1 = __half22float2(wh[1]);
                float2 w2 = __half22float2(wh[2]);
                float2 w3 = __half22float2(wh[3]);
                acc[r] += x0.x * w0.x + x0.y * w0.y + x0.z * w1.x + x0.w * w1.y
                        + x1.x * w2.x + x1.y * w2.y + x1.z * w3.x + x1.w * w3.y;
            }
        }
        __syncthreads();
    }
#pragma unroll
    for (int off = 16; off; off >>= 1)
#pragma unroll
        for (int r = 0; r < 8; r++) acc[r] += __shfl_xor_sync(0xffffffffu, acc[r], off);
    if (lane == 0) {
        *reinterpret_cast<float4*>(g_down + (size_t)row * 8)     = make_float4(acc[0], acc[1], acc[2], acc[3]);
        *reinterpret_cast<float4*>(g_down + (size_t)row * 8 + 4) = make_float4(acc[4], acc[5], acc[6], acc[7]);
    }
}

// ---------------------------------------------------------------------------
// Kernel 3: adapter attention -> g_o = (softmax(qk)v) @ W_o^T  [8192,8]
// ---------------------------------------------------------------------------
__global__ void __launch_bounds__(128) k_attn(const float* __restrict__ Wqkv,
                                              const float* __restrict__ Wo) {
    __shared__ __half2 kv[Sseq * 4];
    __shared__ float wq[96];
    __shared__ float wo[32];
    const int tid = threadIdx.x;
    const int b = blockIdx.y, qt = blockIdx.x;

    if (tid < 96) wq[tid] = Wqkv[tid];
    if (tid < 32) wo[tid] = Wo[tid];
    __syncthreads();

    for (int j = tid; j < Sseq; j += 128) {
        const float* dp = g_down + (size_t)(b * Sseq + j) * 8;
        float4 d0 = *reinterpret_cast<const float4*>(dp);
        float4 d1 = *reinterpret_cast<const float4*>(dp + 4);
        float kd[4], vd[4];
#pragma unroll
        for (int d = 0; d < 4; d++) {
            const float* w = wq + (4 + d) * 8;
            kd[d] = d0.x*w[0] + d0.y*w[1] + d0.z*w[2] + d0.w*w[3]
                  + d1.x*w[4] + d1.y*w[5] + d1.z*w[6] + d1.w*w[7];
            const float* w2 = wq + (8 + d) * 8;
            vd[d] = d0.x*w2[0] + d0.y*w2[1] + d0.z*w2[2] + d0.w*w2[3]
                  + d1.x*w2[4] + d1.y*w2[5] + d1.z*w2[6] + d1.w*w2[7];
        }
        kv[j * 4 + 0] = __floats2half2_rn(kd[0], kd[1]);
        kv[j * 4 + 1] = __floats2half2_rn(kd[2], kd[3]);
        kv[j * 4 + 2] = __floats2half2_rn(vd[0], vd[1]);
        kv[j * 4 + 3] = __floats2half2_rn(vd[2], vd[3]);
    }

    const int qrow = b * Sseq + qt * 128 + tid;
    const float* dq = g_down + (size_t)qrow * 8;
    float4 d0 = *reinterpret_cast<const float4*>(dq);
    float4 d1 = *reinterpret_cast<const float4*>(dq + 4);
    float q[4];
#pragma unroll
    for (int d = 0; d < 4; d++) {
        const float* w = wq + d * 8;
        q[d] = d0.x*w[0] + d0.y*w[1] + d0.z*w[2] + d0.w*w[3]
             + d1.x*w[4] + d1.y*w[5] + d1.z*w[6] + d1.w*w[7];
    }
    __syncthreads();

    float l = 0.f, a0 = 0.f, a1 = 0.f, a2 = 0.f, a3 = 0.f;
    const uint4* kv4 = reinterpret_cast<const uint4*>(kv);
    for (int j = 0; j < Sseq; j++) {
        uint4 pk = kv4[j];
        const __half2* ph = reinterpret_cast<const __half2*>(&pk);
        float2 k01 = __half22float2(ph[0]);
        float2 k23 = __half22float2(ph[1]);
        float2 v01 = __half22float2(ph[2]);
        float2 v23 = __half22float2(ph[3]);
        float s = (q[0]*k01.x + q[1]*k01.y + q[2]*k23.x + q[3]*k23.y) * 0.5f;
        float p = __expf(s);
        l += p;
        a0 += p * v01.x; a1 += p * v01.y; a2 += p * v23.x; a3 += p * v23.y;
    }
    float rl = 1.f / l;
    float c0 = a0 * rl, c1 = a1 * rl, c2 = a2 * rl, c3 = a3 * rl;
    float ov[8];
#pragma unroll
    for (int r = 0; r < 8; r++)
        ov[r] = c0*wo[r*4] + c1*wo[r*4+1] + c2*wo[r*4+2] + c3*wo[r*4+3];
    *reinterpret_cast<float4*>(g_o + (size_t)qrow * 8)     = make_float4(ov[0], ov[1], ov[2], ov[3]);
    *reinterpret_cast<float4*>(g_o + (size_t)qrow * 8 + 4) = make_float4(ov[4], ov[5], ov[6], ov[7]);
}

// ---------------------------------------------------------------------------
// Kernel 4: main GEMM out = xh @ wh^T (+ epilogue: b_pre + (o@W_up^T)*diag_b*4)
// 128x128x32 tiles, fp16 mma.sync m16n8k16, 4-stage cp.async, 2 CTAs/SM.
// ---------------------------------------------------------------------------
#define LDMX4(R0, R1, R2, R3, addr)                                            \
    asm volatile("ldmatrix.sync.aligned.m8n8.x4.shared.b16 {%0,%1,%2,%3}, [%4];" \
                 : "=r"(R0), "=r"(R1), "=r"(R2), "=r"(R3) : "r"(addr))

#define MMA16816(D0, D1, D2, D3, A0, A1, A2, A3, B0, B1)                       \
    asm volatile("mma.sync.aligned.m16n8k16.row.col.f32.f16.f16.f32 "          \
                 "{%0,%1,%2,%3}, {%4,%5,%6,%7}, {%8,%9}, {%0,%1,%2,%3};"       \
                 : "+f"(D0), "+f"(D1), "+f"(D2), "+f"(D3)                      \
                 : "r"(A0), "r"(A1), "r"(A2), "r"(A3), "r"(B0), "r"(B1))

#define CPASYNC16(dst, src)                                                    \
    asm volatile("cp.async.cg.shared.global [%0], [%1], 16;" ::"r"(dst), "l"(src))
#define CPCOMMIT()  asm volatile("cp.async.commit_group;")
#define CPWAIT(N)   asm volatile("cp.async.wait_group %0;" :: "n"(N))

constexpr int LDT = 40;          // smem row stride (halves): 32 + 8 pad
constexpr int STG_H = 128 * LDT; // halves per stage tile (A or B)
constexpr int STAGES = 4;
constexpr size_t SMEM_BYTES = (size_t)2 * STAGES * STG_H * sizeof(__half); // 81920

__device__ __forceinline__ uint32_t smem_u32(const void* p) {
    uint32_t a;
    asm("{ .reg .u64 t; cvta.to.shared.u64 t, %1; cvt.u32.u64 %0, t; }" : "=r"(a) : "l"(p));
    return a;
}

__global__ void __launch_bounds__(256, 2) k_gemm(const float* __restrict__ Wup,
                                                 const float* __restrict__ dbv,
                                                 const float* __restrict__ bpv,
                                                 float* __restrict__ out) {
    extern __shared__ __half sm[];
    const int tid = threadIdx.x;
    const int wid = tid >> 5, lane = tid & 31;
    const int wm = wid >> 2, wn = wid & 3;       // warp grid 2 x 4, warp tile 64x32
    const int m0 = blockIdx.y * 128, n0 = blockIdx.x * 128;

    const uint32_t smb = smem_u32(sm);

    // global->smem load mapping: per stage each thread: 2 A + 2 B 16B chunks
    const int rA = tid >> 2;            // 0..63
    const int cA = (tid & 3) * 8;       // 0,8,16,24 halves
    const __half* pA0 = g_xh + (size_t)(m0 + rA) * Kdim + cA;
    const __half* pA1 = pA0 + (size_t)64 * Kdim;
    const __half* pB0 = g_wh + (size_t)(n0 + rA) * Kdim + cA;
    const __half* pB1 = pB0 + (size_t)64 * Kdim;
    const uint32_t dof0 = (uint32_t)((rA * LDT + cA) * 2);
    const uint32_t dof1 = (uint32_t)(((rA + 64) * LDT + cA) * 2);

#define LOAD_STAGE(J, S) do {                                                  \
    const uint32_t _a = smb + (uint32_t)(S) * (STG_H * 2);                     \
    const uint32_t _b = smb + (uint32_t)(STAGES + (S)) * (STG_H * 2);          \
    const size_t _ko = (size_t)(J) * 32;                                       \
    CPASYNC16(_a + dof0, pA0 + _ko); CPASYNC16(_a + dof1, pA1 + _ko);          \
    CPASYNC16(_b + dof0, pB0 + _ko); CPASYNC16(_b + dof1, pB1 + _ko);          \
} while (0)

    // ldmatrix per-lane offsets
    const int arow = lane & 15, acol = ((lane >> 4) << 3);
    const int brow = (lane & 7) + ((lane >> 4) << 3), bcol = (((lane >> 3) & 1) << 3);

    float acc[4][4][4];
#pragma unroll
    for (int i = 0; i < 4; i++)
#pragma unroll
        for (int j = 0; j < 4; j++)
#pragma unroll
            for (int e = 0; e < 4; e++) acc[i][j][e] = 0.f;

    // prologue: stages 0..2
#pragma unroll
    for (int s = 0; s < STAGES - 1; s++) { LOAD_STAGE(s, s); CPCOMMIT(); }

    const int NIT = Kdim / 32;  // 128
    for (int it = 0; it < NIT; ++it) {
        const int cur = it & (STAGES - 1);
        CPWAIT(STAGES - 2);          // stage `it` complete; 2 groups may fly
        __syncthreads();             // all warps done with slot being refilled
        if (it + STAGES - 1 < NIT) LOAD_STAGE(it + STAGES - 1, (it + STAGES - 1) & (STAGES - 1));
        CPCOMMIT();

        const uint32_t abase = smb + (uint32_t)cur * (STG_H * 2);
        const uint32_t bbase = smb + (uint32_t)(STAGES + cur) * (STG_H * 2);
#pragma unroll
        for (int ks = 0; ks < 2; ks++) {
            uint32_t a[4][4], bf[2][4];
#pragma unroll
            for (int mt = 0; mt < 4; mt++) {
                uint32_t ad = abase + (uint32_t)(((wm * 64 + mt * 16 + arow) * LDT + ks * 16 + acol) * 2);
                LDMX4(a[mt][0], a[mt][1], a[mt][2], a[mt][3], ad);
            }
#pragma unroll
            for (int pt = 0; pt < 2; pt++) {
                uint32_t bd = bbase + (uint32_t)(((wn * 32 + pt * 16 + brow) * LDT + ks * 16 + bcol) * 2);
                LDMX4(bf[pt][0], bf[pt][1], bf[pt][2], bf[pt][3], bd);
            }
#pragma unroll
            for (int mt = 0; mt < 4; mt++)
#pragma unroll
                for (int nt = 0; nt < 4; nt++) {
                    const int pt = nt >> 1, h = (nt & 1) * 2;
                    MMA16816(acc[mt][nt][0], acc[mt][nt][1], acc[mt][nt][2], acc[mt][nt][3],
                             a[mt][0], a[mt][1], a[mt][2], a[mt][3],
                             bf[pt][h], bf[pt][h + 1]);
                }
        }
    }
    CPWAIT(0);
    __syncthreads();

    // Epilogue staging in smem (reuse mainloop buffers)
    float* oS   = reinterpret_cast<float*>(sm);            // [128][8]
    float* wupS = oS + 1024;                               // [128][8]
    float* dbS  = wupS + 1024;                             // [128]
    float* bpS  = dbS + 128;                               // [128]
    {
        float4* d0 = reinterpret_cast<float4*>(oS);
        float4* d1 = reinterpret_cast<float4*>(wupS);
        d0[tid] = reinterpret_cast<const float4*>(g_o + (size_t)m0 * 8)[tid];
        d1[tid] = reinterpret_cast<const float4*>(Wup + (size_t)n0 * 8)[tid];
        if (tid < 128) { dbS[tid] = dbv[n0 + tid] * 4.0f; bpS[tid] = bpv[n0 + tid]; }
    }
    __syncthreads();

    const int g = lane >> 2, tg = lane & 3;
#pragma unroll
    for (int mt = 0; mt < 4; mt++) {
#pragma unroll
        for (int e2 = 0; e2 < 2; e2++) {
            const int r = wm * 64 + mt * 16 + g + e2 * 8;
            float4 o0 = *reinterpret_cast<const float4*>(oS + r * 8);
            float4 o1 = *reinterpret_cast<const float4*>(oS + r * 8 + 4);
#pragma unroll
            for (int nt = 0; nt < 4; nt++) {
                const int c = wn * 32 + nt * 8 + tg * 2;
                float2 res;
#pragma unroll
                for (int cc = 0; cc < 2; cc++) {
                    float4 u0 = *reinterpret_cast<const float4*>(wupS + (c + cc) * 8);
                    float4 u1 = *reinterpret_cast<const float4*>(wupS + (c + cc) * 8 + 4);
                    float ad = o0.x*u0.x + o0.y*u0.y + o0.z*u0.z + o0.w*u0.w
                             + o1.x*u1.x + o1.y*u1.y + o1.z*u1.z + o1.w*u1.w;
                    float v = acc[mt][nt][e2 * 2 + cc] + bpS[c + cc] + ad * dbS[c + cc];
                    if (cc) res.y = v; else res.x = v;
                }
                *reinterpret_cast<float2*>(out + (size_t)(m0 + r) * Ncols + n0 + c) = res;
            }
        }
    }
}

// ---------------------------------------------------------------------------
extern "C" void kernel_launch(void* const* d_in, const int* in_sizes, int n_in,
                              void* d_out, int out_size) {
    const float* x     = (const float*)d_in[0];
    const float* Wpre  = (const float*)d_in[1];
    const float* bpre  = (const float*)d_in[2];
    const float* Wd    = (const float*)d_in[3];
    const float* Wqkv  = (const float*)d_in[4];
    const float* Wo    = (const float*)d_in[5];
    const float* Wup   = (const float*)d_in[6];
    const float* diagb = (const float*)d_in[7];
    float* out = (float*)d_out;

    cudaFuncSetAttribute(k_gemm, cudaFuncAttributeMaxDynamicSharedMemorySize,
                         (int)SMEM_BYTES);

    k_convw<<<(unsigned)(((size_t)Ncols * Kdim) / 2048), 256>>>(Wpre);
    k_down<<<Mrows / 8, 256>>>(x, Wd);
    k_attn<<<dim3(Sseq / 128, Bbat), 128>>>(Wqkv, Wo);
    k_gemm<<<dim3(Ncols / 128, Mrows / 128), 256, SMEM_BYTES>>>(Wup, diagb, bpre, out);
}